// round 13
// baseline (speedup 1.0000x reference)
#include <cuda_runtime.h>
#include <cuda_bf16.h>
#include <cstdint>

#define B_   128
#define T_   512
#define D_   256
#define H_   512
#define G_   2048
#define K0_  768
#define K1_  1024
#define NKT0 (K0_ / 16)      // 48 ktiles
#define NKT1 (K1_ / 16)      // 64 ktiles
#define NCTA 128
#define NTHR 512
#define BH   (B_ * H_)

// ---------------- persistent device scratch -----------------------------------
// Weight fragments: [ntg(256)][ktp][s=hi/lo][lane(32)][8 bf16]  (ktile pairs)
__device__ uint4 g_Wf0[(size_t)256 * NKT0 * 2 * 16];   // 6 MB
__device__ uint4 g_Wf1[(size_t)256 * NKT1 * 2 * 16];   // 8 MB
__device__ float g_b0[G_];
__device__ float g_b1[G_];
// Activations in MMA A-fragment order: per ktile block = [mg(8)][half(2)][lane(32)] uint4
__device__ uint4 g_xf[(size_t)T_ * 16 * 512];          // 64 MB
__device__ uint4 g_h0f[2][32 * 512];                   // 256 KB per buf
__device__ uint4 g_h1f[2][32 * 512];
__device__ unsigned g_count;
__device__ unsigned g_release;

// ---------------- helpers -------------------------------------------------------
__device__ __forceinline__ float sigm(float v) { return 1.f / (1.f + __expf(-v)); }

__device__ __forceinline__ uint32_t pack_split(float v) {
    __nv_bfloat16 h = __float2bfloat16(v);
    __nv_bfloat16 l = __float2bfloat16(v - __bfloat162float(h));
    return (uint32_t)__bfloat16_as_ushort(h) |
           ((uint32_t)__bfloat16_as_ushort(l) << 16);
}

__device__ __forceinline__ uint32_t prmt(uint32_t a, uint32_t b, uint32_t c) {
    uint32_t r;
    asm("prmt.b32 %0, %1, %2, %3;" : "=r"(r) : "r"(a), "r"(b), "r"(c));
    return r;
}

__device__ __forceinline__ void mma16816(float* d, const uint32_t* a, uint2 b) {
    asm volatile(
        "mma.sync.aligned.m16n8k16.row.col.f32.bf16.bf16.f32 "
        "{%0,%1,%2,%3}, {%4,%5,%6,%7}, {%8,%9}, {%0,%1,%2,%3};"
        : "+f"(d[0]), "+f"(d[1]), "+f"(d[2]), "+f"(d[3])
        : "r"(a[0]), "r"(a[1]), "r"(a[2]), "r"(a[3]), "r"(b.x), "r"(b.y));
}

__device__ __forceinline__ void gridBarrier(unsigned target) {
    __syncthreads();
    if (threadIdx.x == 0) {
        __threadfence();
        unsigned t = atomicAdd(&g_count, 1u);
        if (t == (unsigned)(NCTA - 1)) {
            g_count = 0;
            __threadfence();
            atomicAdd(&g_release, 1u);
        } else {
            while ((int)(*(volatile unsigned*)&g_release - target) < 0) {}
        }
        __threadfence();
    }
    __syncthreads();
}

// bf16-split store of W[np][k] into ktile-pair fragment layout (hi plane s=0, lo s=1)
__device__ __forceinline__ void wf_store(__nv_bfloat16* base, int NKTP,
                                         int np, int k, float v) {
    __nv_bfloat16 h = __float2bfloat16(v);
    __nv_bfloat16 l = __float2bfloat16(v - __bfloat162float(h));
    int ntg = np >> 3;
    int ln = ((np & 7) << 2) | ((k >> 1) & 3);   // B-frag: n = lane>>2, q = lane&3
    int kt = k >> 4, ktp = kt >> 1, kh = kt & 1;
    int b = (k >> 3) & 1, e = k & 1;
    size_t o = ((((size_t)ntg * NKTP + ktp) * 2) * 32 + ln) * 8 + kh * 4 + b * 2 + e;
    base[o] = h;
    base[o + 256] = l;   // s=1 plane is +32*8 bf16 (= +32 uint4 = +64 uint2)
}

// ---------------- prep kernels ---------------------------------------------------
// x -> fragment layout; one block per (t, mg), smem tile transpose.
__global__ void prep_x(const float* __restrict__ x) {
    __shared__ float sx[16 * 256];
    int blk = blockIdx.x;           // t*8 + mg
    int t = blk >> 3, mg = blk & 7;
    int tid = threadIdx.x;
    for (int i = tid; i < 16 * 256; i += 256) {
        int r = i >> 8, d = i & 255;
        sx[i] = x[(size_t)(mg * 16 + r) * T_ * D_ + (size_t)t * D_ + d];
    }
    __syncthreads();
    uint32_t* out = (uint32_t*)g_xf;
    for (int j = tid; j < 4096; j += 256) {
        int kt = j >> 8, rem = j & 255;
        int half = rem >> 7, r127 = rem & 127;
        int lane = r127 >> 2, e4 = r127 & 3;
        int r = (lane >> 2) + ((e4 >> 1) << 3);
        int d = kt * 16 + half * 8 + ((lane & 3) << 1) + (e4 & 1);
        out[((((size_t)t * 16 + kt) * 8 + mg) * 2 + half) * 128 + r127] =
            pack_split(sx[r * 256 + d]);
    }
}

// W0[np][k<256] = folded proj; b0
__global__ void prep_w0(const float* __restrict__ wx0, const float* __restrict__ projw,
                        const float* __restrict__ projb, const float* __restrict__ bx0,
                        const float* __restrict__ bh0) {
    int np = blockIdx.x;
    int jcol = np >> 2, q = np & 3;
    int n = q * H_ + jcol;
    int d = threadIdx.x;
    const float* wrow = wx0 + (size_t)n * D_;
    float acc = 0.f;
    for (int j = 0; j < D_; ++j) acc += wrow[j] * projw[(size_t)j * D_ + d];
    wf_store((__nv_bfloat16*)g_Wf0, NKT0 / 2, np, d, acc);
    if (d == 0) {
        float bb = bx0[n] + bh0[n];
        for (int j = 0; j < D_; ++j) bb += wrow[j] * projb[j];
        g_b0[np] = bb;
    }
}

// W0[np][k>=256] = wh0 ; W1 = [wx1|wh1] ; b1
__global__ void prep_rest(const float* __restrict__ wh0, const float* __restrict__ wx1,
                          const float* __restrict__ wh1, const float* __restrict__ bx1,
                          const float* __restrict__ bh1) {
    const int total = G_ * H_ + G_ * K1_ + G_;
    for (int i = blockIdx.x * blockDim.x + threadIdx.x; i < total;
         i += gridDim.x * blockDim.x) {
        if (i < G_ * H_) {
            int np = i / H_, k = i % H_;
            int n = (np & 3) * H_ + (np >> 2);
            wf_store((__nv_bfloat16*)g_Wf0, NKT0 / 2, np, D_ + k,
                     wh0[(size_t)n * H_ + k]);
        } else if (i < G_ * H_ + G_ * K1_) {
            int r = i - G_ * H_;
            int np = r / K1_, k = r % K1_;
            int n = (np & 3) * H_ + (np >> 2);
            float v = (k < H_) ? wx1[(size_t)n * H_ + k]
                               : wh1[(size_t)n * H_ + (k - H_)];
            wf_store((__nv_bfloat16*)g_Wf1, NKT1 / 2, np, k, v);
        } else {
            int np = i - G_ * H_ - G_ * K1_;
            int n = (np & 3) * H_ + (np >> 2);
            g_b1[np] = bx1[n] + bh1[n];
        }
    }
}

// ---------------- one LSTM phase: K-split fragment mma + merge + cell epilogue ---
// 16 warps = 8 M-groups x 2 K-groups. Each warp: M=16 x N=32 over NKT/2 ktiles.
template <int NKT>
__device__ void lstm_phase(const uint32_t* __restrict__ sW,
    const uint4* __restrict__ pA, const uint4* __restrict__ pB, int split,
    uint4* __restrict__ hOutF, float* cst,
    const float* __restrict__ sbias, float4* __restrict__ merge,
    uint32_t* __restrict__ bounce, int lc) {
    constexpr int NKTP = NKT / 2;
    constexpr int NKTH = NKT / 2;          // ktiles per k-group warp
    const int tid = threadIdx.x;
    const int lane = tid & 31, w = tid >> 5;
    const int mg = w & 7, kgrp = w >> 3;
    const int mgl = mg * 64 + lane;
    const int ktbase = kgrp * NKTH;

    float acc[4][4];
#pragma unroll
    for (int j = 0; j < 4; ++j)
#pragma unroll
        for (int k = 0; k < 4; ++k) acc[j][k] = 0.f;

    uint4 ab[4][2];
#pragma unroll
    for (int p = 0; p < 4; ++p) {
        int kt = ktbase + p;
        const uint4* s = ((kt < split) ? pA + (size_t)kt * 512
                                       : pB + (size_t)(kt - split) * 512) + mgl;
        ab[p][0] = s[0];
        ab[p][1] = s[32];
    }
    const uint2* sW2 = (const uint2*)sW;

#pragma unroll 4
    for (int kk = 0; kk < NKTH; ++kk) {
        int kt = ktbase + kk;
        int ktp = kt >> 1, half = kt & 1;

        uint2 bh[4], bl[4];
#pragma unroll
        for (int nt = 0; nt < 4; ++nt) {
            size_t u2 = ((size_t)((nt * NKTP + ktp) * 2) * 32 + lane) * 2 + half;
            bh[nt] = sW2[u2];
            bl[nt] = sW2[u2 + 64];   // lo plane: +32 uint4 = +64 uint2 (R12 bug fixed)
        }
        uint32_t* cur = (uint32_t*)ab[kk & 3];
        uint32_t ah[4], al[4];
#pragma unroll
        for (int j = 0; j < 4; ++j) {
            ah[j] = prmt(cur[2 * j], cur[2 * j + 1], 0x5410);
            al[j] = prmt(cur[2 * j], cur[2 * j + 1], 0x7632);
        }
        if (kk + 4 < NKTH) {
            int kn = kt + 4;
            const uint4* s = ((kn < split) ? pA + (size_t)kn * 512
                                           : pB + (size_t)(kn - split) * 512) + mgl;
            ab[kk & 3][0] = s[0];
            ab[kk & 3][1] = s[32];
        }
        // pass 1: hi·hi   pass 2: lo·hi   pass 3: hi·lo
#pragma unroll
        for (int nt = 0; nt < 4; ++nt) mma16816(acc[nt], ah, bh[nt]);
#pragma unroll
        for (int nt = 0; nt < 4; ++nt) mma16816(acc[nt], al, bh[nt]);
#pragma unroll
        for (int nt = 0; nt < 4; ++nt) mma16816(acc[nt], ah, bl[nt]);
    }

    // merge: k-group 1 deposits partials (conflict-free lane-contiguous planes)
    if (kgrp == 1) {
#pragma unroll
        for (int j = 0; j < 4; ++j)
            merge[j * 256 + mg * 32 + lane] =
                make_float4(acc[j][0], acc[j][1], acc[j][2], acc[j][3]);
    }
    __syncthreads();

    if (kgrp == 0) {
#pragma unroll
        for (int j = 0; j < 4; ++j) {
            float4 v = merge[j * 256 + mg * 32 + lane];
            acc[j][0] += v.x; acc[j][1] += v.y;
            acc[j][2] += v.z; acc[j][3] += v.w;
        }
        // epilogue: even lanes own cells; (g,o) from odd neighbor via shfl.xor(1)
        const int q = lane & 3;
#pragma unroll
        for (int nt = 0; nt < 4; ++nt) {
            float* A = acc[nt];
            float e0 = __shfl_xor_sync(0xffffffffu, A[0], 1);
            float e1 = __shfl_xor_sync(0xffffffffu, A[1], 1);
            float e2 = __shfl_xor_sync(0xffffffffu, A[2], 1);
            float e3 = __shfl_xor_sync(0xffffffffu, A[3], 1);
            if (!(lane & 1)) {
                int nb = nt * 8 + 2 * q;
                float bi = sbias[nb],     bfv = sbias[nb + 1];
                float bg = sbias[nb + 2], bo  = sbias[nb + 3];
                int jc = nt * 2 + (q >> 1);
                int row = mg * 16 + (lane >> 2);
#pragma unroll
                for (int rp = 0; rp < 2; ++rp) {
                    float iv = A[rp * 2 + 0] + bi;
                    float fv = A[rp * 2 + 1] + bfv;
                    float gv = (rp ? e2 : e0) + bg;
                    float ov = (rp ? e3 : e1) + bo;
                    int ci = rp * 4 + nt;
                    float cn = sigm(fv) * cst[ci] + sigm(iv) * tanhf(gv);
                    cst[ci] = cn;
                    bounce[(row + rp * 8) * 8 + jc] =
                        pack_split(sigm(ov) * tanhf(cn));
                }
            }
        }
    }
    __syncthreads();
    if (tid < 256) {   // fragment-order h store: one uint4 per thread, coalesced
        int w8 = tid >> 5;
        int rlo = lane >> 2, q2 = lane & 3;
        int row = w8 * 16 + rlo;
        uint4 v;
        v.x = bounce[row * 8 + 2 * q2];
        v.y = bounce[row * 8 + 2 * q2 + 1];
        v.z = bounce[(row + 8) * 8 + 2 * q2];
        v.w = bounce[(row + 8) * 8 + 2 * q2 + 1];
        hOutF[(size_t)(lc >> 1) * 512 + w8 * 64 + (lc & 1) * 32 + lane] = v;
    }
}

// ---------------- persistent main kernel -----------------------------------------
__global__ void __launch_bounds__(NTHR, 1) lstm_main() {
    extern __shared__ uint32_t smw[];          // weights | merge | bounce
    __shared__ float s_bias[32];
    float4* merge = (float4*)(smw + 32768);    // 16 KB after 128 KB weights
    uint32_t* bounce = smw + 32768 + 4096;     // 4 KB after merge

    const int cta = blockIdx.x, tid = threadIdx.x;
    const bool isL1 = (cta >= 64);
    const int lc = isL1 ? cta - 64 : cta;

    // load resident weight fragment slice (contiguous)
    {
        const uint4* src = isL1 ? g_Wf1 : g_Wf0;
        const int NKT = isL1 ? NKT1 : NKT0;
        const uint4* s = src + (size_t)lc * NKT * 128;
        uint4* d = (uint4*)smw;
        for (int i = tid; i < NKT * 128; i += NTHR) d[i] = s[i];
        const float* gb = isL1 ? g_b1 : g_b0;
        if (tid < 32) s_bias[tid] = gb[lc * 32 + tid];
    }
    // zero h fragment buffers each launch (deterministic)
    {
        uint32_t* hz0 = (uint32_t*)g_h0f;
        uint32_t* hz1 = (uint32_t*)g_h1f;
        for (int i = cta * NTHR + tid; i < 2 * 32 * 512 * 4; i += NCTA * NTHR) {
            hz0[i] = 0u;
            hz1[i] = 0u;
        }
    }

    unsigned relBase = *(volatile unsigned*)&g_release;
    unsigned gen = 0;
    float cst[8];
#pragma unroll
    for (int i = 0; i < 8; ++i) cst[i] = 0.f;

    gridBarrier(relBase + ++gen);

    for (int phase = 0; phase <= T_; ++phase) {
        if (!isL1) {
            if (phase < T_) {
                int t = phase;
                lstm_phase<NKT0>(smw, g_xf + (size_t)t * 16 * 512,
                                 g_h0f[(t & 1) ^ 1], 16,
                                 g_h0f[t & 1], cst, s_bias, merge, bounce, lc);
            }
        } else if (phase >= 1) {
            int t = phase - 1;
            lstm_phase<NKT1>(smw, g_h0f[t & 1],
                             g_h1f[(t & 1) ^ 1], 32,
                             g_h1f[t & 1], cst, s_bias, merge, bounce, lc);
        }
        gridBarrier(relBase + ++gen);
    }
}

// ---------------- FC head ----------------------------------------------------------
__global__ void fc_head(const float* __restrict__ fc1w, const float* __restrict__ fc1b,
                        const float* __restrict__ fc2w, const float* __restrict__ fc2b,
                        float* __restrict__ out) {
    __shared__ float hsh[H_];
    __shared__ float hid[32];
    int b = blockIdx.x, tid = threadIdx.x;
    const uint32_t* hf = (const uint32_t*)g_h1f[1];   // t=511 odd -> buf1
#pragma unroll
    for (int rr = 0; rr < 2; ++rr) {
        int col = tid + rr * 256;
        int kt = col >> 4, c16 = col & 15;
        int half = c16 >> 3, q = (c16 >> 1) & 3, e = c16 & 1;
        int r = b & 15, mg = b >> 4;
        int lane2 = ((r & 7) << 2) | q;
        int e4 = (((r >> 3) & 1) << 1) | e;
        uint32_t u = hf[((((size_t)kt * 8 + mg) * 2 + half) * 32 + lane2) * 4 + e4];
        hsh[col] =
            __bfloat162float(__ushort_as_bfloat16((unsigned short)(u & 0xFFFFu))) +
            __bfloat162float(__ushort_as_bfloat16((unsigned short)(u >> 16)));
    }
    __syncthreads();
    int w = tid >> 5, lane = tid & 31;
    for (int j = w; j < 32; j += 8) {
        const float* wr = fc1w + (size_t)j * H_;
        float s = 0.f;
        for (int k = lane; k < H_; k += 32) s += hsh[k] * wr[k];
#pragma unroll
        for (int off = 16; off; off >>= 1) s += __shfl_xor_sync(0xffffffffu, s, off);
        if (lane == 0) hid[j] = fmaxf(s + fc1b[j], 0.f) * fc2w[j];
    }
    __syncthreads();
    if (tid < 32) {
        float v = hid[tid];
#pragma unroll
        for (int off = 16; off; off >>= 1) v += __shfl_xor_sync(0xffffffffu, v, off);
        if (tid == 0) out[b] = v + fc2b[0];
    }
}

// ---------------- launch -------------------------------------------------------------
extern "C" void kernel_launch(void* const* d_in, const int* in_sizes, int n_in,
                              void* d_out, int out_size) {
    const float* x     = (const float*)d_in[0];
    const float* projw = (const float*)d_in[1];
    const float* projb = (const float*)d_in[2];
    const float* wx0   = (const float*)d_in[3];
    const float* bx0   = (const float*)d_in[4];
    const float* wh0   = (const float*)d_in[5];
    const float* bh0   = (const float*)d_in[6];
    const float* wx1   = (const float*)d_in[7];
    const float* bx1   = (const float*)d_in[8];
    const float* wh1   = (const float*)d_in[9];
    const float* bh1   = (const float*)d_in[10];
    const float* fc1w  = (const float*)d_in[11];
    const float* fc1b  = (const float*)d_in[12];
    const float* fc2w  = (const float*)d_in[13];
    const float* fc2b  = (const float*)d_in[14];
    float* out = (float*)d_out;

    const int SMEM_BYTES = 131072 + 16384 + 4096;  // weights + merge + bounce
    cudaFuncSetAttribute(lstm_main, cudaFuncAttributeMaxDynamicSharedMemorySize,
                         SMEM_BYTES);

    prep_x<<<T_ * 8, 256>>>(x);
    prep_w0<<<G_, D_>>>(wx0, projw, projb, bx0, bh0);
    prep_rest<<<2048, 256>>>(wh0, wx1, wh1, bx1, bh1);
    lstm_main<<<NCTA, NTHR, SMEM_BYTES>>>();
    fc_head<<<B_, 256>>>(fc1w, fc1b, fc2w, fc2b, out);
}

// round 14
// speedup vs baseline: 1.1893x; 1.1893x over previous
#include <cuda_runtime.h>
#include <cuda_bf16.h>
#include <cstdint>

#define B_   128
#define T_   512
#define D_   256
#define H_   512
#define G_   2048
#define K0_  768
#define K1_  1024
#define NKT0 (K0_ / 16)      // 48 ktiles
#define NKT1 (K1_ / 16)      // 64 ktiles
#define NCTA 128
#define NTHR 512
#define BH   (B_ * H_)

// ---------------- persistent device scratch -----------------------------------
// Weight fragments: [ntg(256)][ktp][s=hi/lo][lane(32)][8 bf16]  (ktile pairs)
__device__ uint4 g_Wf0[(size_t)256 * NKT0 * 2 * 16];   // 6 MB
__device__ uint4 g_Wf1[(size_t)256 * NKT1 * 2 * 16];   // 8 MB
__device__ float g_b0[G_];
__device__ float g_b1[G_];
// Activations, PRE-SPLIT fragment order: per ktile block = [mg(8)][s=hi/lo(2)][lane(32)] uint4
// (uint4 .xy derive from k-half 0, .zw from k-half 1 of the ktile)
__device__ uint4 g_xf[(size_t)T_ * 16 * 512];          // 64 MB
__device__ uint4 g_h0f[2][32 * 512];                   // 256 KB per buf
__device__ uint4 g_h1f[2][32 * 512];
__device__ unsigned g_count;
__device__ unsigned g_release;

// ---------------- helpers -------------------------------------------------------
__device__ __forceinline__ float sigm(float v) { return 1.f / (1.f + __expf(-v)); }

__device__ __forceinline__ uint32_t pack_split(float v) {
    __nv_bfloat16 h = __float2bfloat16(v);
    __nv_bfloat16 l = __float2bfloat16(v - __bfloat162float(h));
    return (uint32_t)__bfloat16_as_ushort(h) |
           ((uint32_t)__bfloat16_as_ushort(l) << 16);
}

__device__ __forceinline__ uint32_t prmt(uint32_t a, uint32_t b, uint32_t c) {
    uint32_t r;
    asm("prmt.b32 %0, %1, %2, %3;" : "=r"(r) : "r"(a), "r"(b), "r"(c));
    return r;
}

__device__ __forceinline__ void mma16816(float* d, const uint32_t* a, uint2 b) {
    asm volatile(
        "mma.sync.aligned.m16n8k16.row.col.f32.bf16.bf16.f32 "
        "{%0,%1,%2,%3}, {%4,%5,%6,%7}, {%8,%9}, {%0,%1,%2,%3};"
        : "+f"(d[0]), "+f"(d[1]), "+f"(d[2]), "+f"(d[3])
        : "r"(a[0]), "r"(a[1]), "r"(a[2]), "r"(a[3]), "r"(b.x), "r"(b.y));
}

__device__ __forceinline__ void gridBarrier(unsigned target) {
    __syncthreads();
    if (threadIdx.x == 0) {
        __threadfence();
        unsigned t = atomicAdd(&g_count, 1u);
        if (t == (unsigned)(NCTA - 1)) {
            g_count = 0;
            __threadfence();
            atomicAdd(&g_release, 1u);
        } else {
            while ((int)(*(volatile unsigned*)&g_release - target) < 0) {}
        }
        __threadfence();
    }
    __syncthreads();
}

// bf16-split store of W[np][k] into ktile-pair fragment layout (hi plane s=0, lo s=1)
__device__ __forceinline__ void wf_store(__nv_bfloat16* base, int NKTP,
                                         int np, int k, float v) {
    __nv_bfloat16 h = __float2bfloat16(v);
    __nv_bfloat16 l = __float2bfloat16(v - __bfloat162float(h));
    int ntg = np >> 3;
    int ln = ((np & 7) << 2) | ((k >> 1) & 3);   // B-frag: n = lane>>2, q = lane&3
    int kt = k >> 4, ktp = kt >> 1, kh = kt & 1;
    int b = (k >> 3) & 1, e = k & 1;
    size_t o = ((((size_t)ntg * NKTP + ktp) * 2) * 32 + ln) * 8 + kh * 4 + b * 2 + e;
    base[o] = h;
    base[o + 256] = l;   // s=1 plane is +32*8 bf16 (= +32 uint4)
}

// ---------------- prep kernels ---------------------------------------------------
// x -> PRE-SPLIT fragment layout; one block per (t, mg), smem tile transpose.
__global__ void prep_x(const float* __restrict__ x) {
    __shared__ float sx[16 * 256];
    int blk = blockIdx.x;           // t*8 + mg
    int t = blk >> 3, mg = blk & 7;
    int tid = threadIdx.x;
    for (int i = tid; i < 16 * 256; i += 256) {
        int r = i >> 8, d = i & 255;
        sx[i] = x[(size_t)(mg * 16 + r) * T_ * D_ + (size_t)t * D_ + d];
    }
    __syncthreads();
    uint4* out = g_xf + (size_t)t * 16 * 512;
    for (int i = tid; i < 512; i += 256) {   // (kt, lane)
        int kt = i >> 5, lane = i & 31;
        uint32_t hi[4], lo[4];
#pragma unroll
        for (int j = 0; j < 4; ++j) {
            int r = (lane >> 2) + (j & 1) * 8;
            int d0 = kt * 16 + (j >> 1) * 8 + ((lane & 3) << 1);
            uint32_t p0 = pack_split(sx[r * 256 + d0]);
            uint32_t p1 = pack_split(sx[r * 256 + d0 + 1]);
            hi[j] = prmt(p0, p1, 0x5410);
            lo[j] = prmt(p0, p1, 0x7632);
        }
        out[(size_t)kt * 512 + mg * 64 + lane] =
            make_uint4(hi[0], hi[1], hi[2], hi[3]);
        out[(size_t)kt * 512 + mg * 64 + 32 + lane] =
            make_uint4(lo[0], lo[1], lo[2], lo[3]);
    }
}

// W0[np][k<256] = folded proj; b0
__global__ void prep_w0(const float* __restrict__ wx0, const float* __restrict__ projw,
                        const float* __restrict__ projb, const float* __restrict__ bx0,
                        const float* __restrict__ bh0) {
    int np = blockIdx.x;
    int jcol = np >> 2, q = np & 3;
    int n = q * H_ + jcol;
    int d = threadIdx.x;
    const float* wrow = wx0 + (size_t)n * D_;
    float acc = 0.f;
    for (int j = 0; j < D_; ++j) acc += wrow[j] * projw[(size_t)j * D_ + d];
    wf_store((__nv_bfloat16*)g_Wf0, NKT0 / 2, np, d, acc);
    if (d == 0) {
        float bb = bx0[n] + bh0[n];
        for (int j = 0; j < D_; ++j) bb += wrow[j] * projb[j];
        g_b0[np] = bb;
    }
}

// W0[np][k>=256] = wh0 ; W1 = [wx1|wh1] ; b1
__global__ void prep_rest(const float* __restrict__ wh0, const float* __restrict__ wx1,
                          const float* __restrict__ wh1, const float* __restrict__ bx1,
                          const float* __restrict__ bh1) {
    const int total = G_ * H_ + G_ * K1_ + G_;
    for (int i = blockIdx.x * blockDim.x + threadIdx.x; i < total;
         i += gridDim.x * blockDim.x) {
        if (i < G_ * H_) {
            int np = i / H_, k = i % H_;
            int n = (np & 3) * H_ + (np >> 2);
            wf_store((__nv_bfloat16*)g_Wf0, NKT0 / 2, np, D_ + k,
                     wh0[(size_t)n * H_ + k]);
        } else if (i < G_ * H_ + G_ * K1_) {
            int r = i - G_ * H_;
            int np = r / K1_, k = r % K1_;
            int n = (np & 3) * H_ + (np >> 2);
            float v = (k < H_) ? wx1[(size_t)n * H_ + k]
                               : wh1[(size_t)n * H_ + (k - H_)];
            wf_store((__nv_bfloat16*)g_Wf1, NKT1 / 2, np, k, v);
        } else {
            int np = i - G_ * H_ - G_ * K1_;
            int n = (np & 3) * H_ + (np >> 2);
            g_b1[np] = bx1[n] + bh1[n];
        }
    }
}

// ---------------- A fragment loads (pre-split hi/lo uint4, direct from global) ---
__device__ __forceinline__ void ldA2(uint4* a2, int kt,
    const uint4* __restrict__ pA, const uint4* __restrict__ pB, int split,
    int mgl) {
    const uint4* s = ((kt < split) ? pA + (size_t)kt * 512
                                   : pB + (size_t)(kt - split) * 512) + mgl;
    a2[0] = s[0];    // hi fragment
    a2[1] = s[32];   // lo fragment
}

// ---------------- one LSTM phase: K-split fragment mma + merge + cell epilogue ---
// 16 warps = 8 M-groups x 2 K-groups; each warp M=16 x N=32 over NKT/2 ktiles.
// B read as uint4 per ktile-PAIR (LDS.128); A pre-split (no PRMT in hot loop).
template <int NKT>
__device__ void lstm_phase(const uint32_t* __restrict__ sW,
    const uint4* __restrict__ pA, const uint4* __restrict__ pB, int split,
    uint4* __restrict__ hOutF, float* cst,
    const float* __restrict__ sbias, float4* __restrict__ merge,
    uint32_t* __restrict__ bounce, int lc) {
    constexpr int NKTP  = NKT / 2;   // ktile pairs total
    constexpr int NKTH  = NKT / 2;   // ktiles per k-group
    constexpr int NKTP2 = NKT / 4;   // ktile pairs per k-group
    const int tid = threadIdx.x;
    const int lane = tid & 31, w = tid >> 5;
    const int mg = w & 7, kgrp = w >> 3;
    const int mgl = mg * 64 + lane;
    const int ktbase = kgrp * NKTH;

    float acc[4][4];
#pragma unroll
    for (int j = 0; j < 4; ++j)
#pragma unroll
        for (int k = 0; k < 4; ++k) acc[j][k] = 0.f;

    uint4 ab[4][2];
#pragma unroll
    for (int p = 0; p < 4; ++p)
        ldA2(ab[p], ktbase + p, pA, pB, split, mgl);

    const uint4* sW4 = (const uint4*)sW;

#pragma unroll 2
    for (int ktpl = 0; ktpl < NKTP2; ++ktpl) {
        int ktp = kgrp * NKTP2 + ktpl;
        uint4 bh[4], bl[4];
#pragma unroll
        for (int nt = 0; nt < 4; ++nt) {
            const uint4* wp = sW4 + (size_t)((nt * NKTP + ktp) * 2) * 32 + lane;
            bh[nt] = wp[0];
            bl[nt] = wp[32];
        }
#pragma unroll
        for (int half = 0; half < 2; ++half) {
            int kk = ktpl * 2 + half;
            const uint32_t* ah = (const uint32_t*)&ab[kk & 3][0];
            const uint32_t* al = (const uint32_t*)&ab[kk & 3][1];
            // pass 1: hi·hi   pass 2: lo·hi   pass 3: hi·lo
#pragma unroll
            for (int nt = 0; nt < 4; ++nt) {
                uint2 b2 = half ? make_uint2(bh[nt].z, bh[nt].w)
                                : make_uint2(bh[nt].x, bh[nt].y);
                mma16816(acc[nt], ah, b2);
            }
#pragma unroll
            for (int nt = 0; nt < 4; ++nt) {
                uint2 b2 = half ? make_uint2(bh[nt].z, bh[nt].w)
                                : make_uint2(bh[nt].x, bh[nt].y);
                mma16816(acc[nt], al, b2);
            }
#pragma unroll
            for (int nt = 0; nt < 4; ++nt) {
                uint2 b2 = half ? make_uint2(bl[nt].z, bl[nt].w)
                                : make_uint2(bl[nt].x, bl[nt].y);
                mma16816(acc[nt], ah, b2);
            }
            if (kk + 4 < NKTH)   // WAR on ab handled by scoreboard (after reads)
                ldA2(ab[kk & 3], ktbase + kk + 4, pA, pB, split, mgl);
        }
    }

    // merge: k-group 1 deposits partials (conflict-free lane-contiguous planes)
    if (kgrp == 1) {
#pragma unroll
        for (int j = 0; j < 4; ++j)
            merge[j * 256 + mg * 32 + lane] =
                make_float4(acc[j][0], acc[j][1], acc[j][2], acc[j][3]);
    }
    __syncthreads();

    if (kgrp == 0) {
#pragma unroll
        for (int j = 0; j < 4; ++j) {
            float4 v = merge[j * 256 + mg * 32 + lane];
            acc[j][0] += v.x; acc[j][1] += v.y;
            acc[j][2] += v.z; acc[j][3] += v.w;
        }
        // epilogue: even lanes own cells; (g,o) from odd neighbor via shfl.xor(1)
        const int q = lane & 3;
#pragma unroll
        for (int nt = 0; nt < 4; ++nt) {
            float* A = acc[nt];
            float e0 = __shfl_xor_sync(0xffffffffu, A[0], 1);
            float e1 = __shfl_xor_sync(0xffffffffu, A[1], 1);
            float e2 = __shfl_xor_sync(0xffffffffu, A[2], 1);
            float e3 = __shfl_xor_sync(0xffffffffu, A[3], 1);
            if (!(lane & 1)) {
                int nb = nt * 8 + 2 * q;
                float bi = sbias[nb],     bfv = sbias[nb + 1];
                float bg = sbias[nb + 2], bo  = sbias[nb + 3];
                int jc = nt * 2 + (q >> 1);
                int row = mg * 16 + (lane >> 2);
#pragma unroll
                for (int rp = 0; rp < 2; ++rp) {
                    float iv = A[rp * 2 + 0] + bi;
                    float fv = A[rp * 2 + 1] + bfv;
                    float gv = (rp ? e2 : e0) + bg;
                    float ov = (rp ? e3 : e1) + bo;
                    int ci = rp * 4 + nt;
                    float cn = sigm(fv) * cst[ci] + sigm(iv) * tanhf(gv);
                    cst[ci] = cn;
                    bounce[(row + rp * 8) * 8 + jc] =
                        pack_split(sigm(ov) * tanhf(cn));
                }
            }
        }
    }
    __syncthreads();
    if (tid < 256) {   // pre-split h store: hi/lo uint2 per thread, coalesced
        int w8 = tid >> 5;
        int ln = tid & 31;
        int rlo = ln >> 2, q2 = ln & 3;
        int row = w8 * 16 + rlo;
        uint32_t c0 = bounce[row * 8 + 2 * q2];
        uint32_t c1 = bounce[row * 8 + 2 * q2 + 1];
        uint32_t c2 = bounce[(row + 8) * 8 + 2 * q2];
        uint32_t c3 = bounce[(row + 8) * 8 + 2 * q2 + 1];
        uint2 hiv = make_uint2(prmt(c0, c1, 0x5410), prmt(c2, c3, 0x5410));
        uint2 lov = make_uint2(prmt(c0, c1, 0x7632), prmt(c2, c3, 0x7632));
        int kt = lc >> 1, half = lc & 1;
        uint2* o = (uint2*)hOutF;
        size_t bidx = (size_t)kt * 512 + w8 * 64 + ln;
        o[2 * bidx + half] = hiv;                 // hi plane, k-half slot
        o[2 * (bidx + 32) + half] = lov;          // lo plane
    }
}

// ---------------- persistent main kernel -----------------------------------------
__global__ void __launch_bounds__(NTHR, 1) lstm_main() {
    extern __shared__ uint32_t smw[];          // weights | merge | bounce
    __shared__ float s_bias[32];
    float4* merge = (float4*)(smw + 32768);    // 16 KB after 128 KB weights
    uint32_t* bounce = smw + 32768 + 4096;     // 4 KB after merge

    const int cta = blockIdx.x, tid = threadIdx.x;
    const bool isL1 = (cta >= 64);
    const int lc = isL1 ? cta - 64 : cta;

    // load resident weight fragment slice (contiguous)
    {
        const uint4* src = isL1 ? g_Wf1 : g_Wf0;
        const int NKT = isL1 ? NKT1 : NKT0;
        const uint4* s = src + (size_t)lc * NKT * 128;
        uint4* d = (uint4*)smw;
        for (int i = tid; i < NKT * 128; i += NTHR) d[i] = s[i];
        const float* gb = isL1 ? g_b1 : g_b0;
        if (tid < 32) s_bias[tid] = gb[lc * 32 + tid];
    }
    // zero h fragment buffers each launch (deterministic)
    {
        uint32_t* hz0 = (uint32_t*)g_h0f;
        uint32_t* hz1 = (uint32_t*)g_h1f;
        for (int i = cta * NTHR + tid; i < 2 * 32 * 512 * 4; i += NCTA * NTHR) {
            hz0[i] = 0u;
            hz1[i] = 0u;
        }
    }

    unsigned relBase = *(volatile unsigned*)&g_release;
    unsigned gen = 0;
    float cst[8];
#pragma unroll
    for (int i = 0; i < 8; ++i) cst[i] = 0.f;

    gridBarrier(relBase + ++gen);

    for (int phase = 0; phase <= T_; ++phase) {
        if (!isL1) {
            if (phase < T_) {
                int t = phase;
                lstm_phase<NKT0>(smw, g_xf + (size_t)t * 16 * 512,
                                 g_h0f[(t & 1) ^ 1], 16,
                                 g_h0f[t & 1], cst, s_bias, merge, bounce, lc);
            }
        } else if (phase >= 1) {
            int t = phase - 1;
            lstm_phase<NKT1>(smw, g_h0f[t & 1],
                             g_h1f[(t & 1) ^ 1], 32,
                             g_h1f[t & 1], cst, s_bias, merge, bounce, lc);
        }
        gridBarrier(relBase + ++gen);
    }
}

// ---------------- FC head ----------------------------------------------------------
__global__ void fc_head(const float* __restrict__ fc1w, const float* __restrict__ fc1b,
                        const float* __restrict__ fc2w, const float* __restrict__ fc2b,
                        float* __restrict__ out) {
    __shared__ float hsh[H_];
    __shared__ float hid[32];
    int b = blockIdx.x, tid = threadIdx.x;
    const uint32_t* hf = (const uint32_t*)g_h1f[1];   // t=511 odd -> buf1
#pragma unroll
    for (int rr = 0; rr < 2; ++rr) {
        int col = tid + rr * 256;
        int kt = col >> 4, k16 = col & 15;
        int half = k16 >> 3, q = (k16 >> 1) & 3, e = k16 & 1;
        int r = b & 15, mg = b >> 4;
        int lane2 = ((r & 7) << 2) | q;
        int j = half * 2 + ((r >> 3) & 1);
        size_t u32i = ((size_t)kt * 512 + mg * 64 + lane2) * 4 + j;
        uint32_t uh = hf[u32i];          // hi plane
        uint32_t ul = hf[u32i + 128];    // lo plane (+32 uint4)
        unsigned short sh = e ? (unsigned short)(uh >> 16) : (unsigned short)(uh & 0xFFFFu);
        unsigned short sl = e ? (unsigned short)(ul >> 16) : (unsigned short)(ul & 0xFFFFu);
        hsh[col] = __bfloat162float(__ushort_as_bfloat16(sh)) +
                   __bfloat162float(__ushort_as_bfloat16(sl));
    }
    __syncthreads();
    int w = tid >> 5, lane = tid & 31;
    for (int j = w; j < 32; j += 8) {
        const float* wr = fc1w + (size_t)j * H_;
        float s = 0.f;
        for (int k = lane; k < H_; k += 32) s += hsh[k] * wr[k];
#pragma unroll
        for (int off = 16; off; off >>= 1) s += __shfl_xor_sync(0xffffffffu, s, off);
        if (lane == 0) hid[j] = fmaxf(s + fc1b[j], 0.f) * fc2w[j];
    }
    __syncthreads();
    if (tid < 32) {
        float v = hid[tid];
#pragma unroll
        for (int off = 16; off; off >>= 1) v += __shfl_xor_sync(0xffffffffu, v, off);
        if (tid == 0) out[b] = v + fc2b[0];
    }
}

// ---------------- launch -------------------------------------------------------------
extern "C" void kernel_launch(void* const* d_in, const int* in_sizes, int n_in,
                              void* d_out, int out_size) {
    const float* x     = (const float*)d_in[0];
    const float* projw = (const float*)d_in[1];
    const float* projb = (const float*)d_in[2];
    const float* wx0   = (const float*)d_in[3];
    const float* bx0   = (const float*)d_in[4];
    const float* wh0   = (const float*)d_in[5];
    const float* bh0   = (const float*)d_in[6];
    const float* wx1   = (const float*)d_in[7];
    const float* bx1   = (const float*)d_in[8];
    const float* wh1   = (const float*)d_in[9];
    const float* bh1   = (const float*)d_in[10];
    const float* fc1w  = (const float*)d_in[11];
    const float* fc1b  = (const float*)d_in[12];
    const float* fc2w  = (const float*)d_in[13];
    const float* fc2b  = (const float*)d_in[14];
    float* out = (float*)d_out;

    const int SMEM_BYTES = 131072 + 16384 + 4096;  // weights + merge + bounce
    cudaFuncSetAttribute(lstm_main, cudaFuncAttributeMaxDynamicSharedMemorySize,
                         SMEM_BYTES);

    prep_x<<<T_ * 8, 256>>>(x);
    prep_w0<<<G_, D_>>>(wx0, projw, projb, bx0, bh0);
    prep_rest<<<2048, 256>>>(wh0, wx1, wh1, bx1, bh1);
    lstm_main<<<NCTA, NTHR, SMEM_BYTES>>>();
    fc_head<<<B_, 256>>>(fc1w, fc1b, fc2w, fc2b, out);
}

// round 15
// speedup vs baseline: 1.3787x; 1.1592x over previous
#include <cuda_runtime.h>
#include <cuda_bf16.h>
#include <cstdint>

#define B_   128
#define T_   512
#define D_   256
#define H_   512
#define G_   2048
#define K0_  768
#define K1_  1024
#define NKT0 (K0_ / 16)      // 48 ktiles
#define NKT1 (K1_ / 16)      // 64 ktiles
#define NCTA 128
#define NTHR 512
#define BH   (B_ * H_)

// dynamic smem layout (uint32 indices)
#define PART_F   16896                   // 128 blocks * 132 floats
#define OFF_BOUNCE 16896                 // u32 idx of bounce
#define OFF_W      (16896 + 1024)        // u32 idx of weights (17920; 16B aligned)

// ---------------- persistent device scratch -----------------------------------
// Weight fragments: [ntg(256)][ktp][s=hi/lo][lane(32)][8 bf16]  (ktile pairs)
__device__ uint4 g_Wf0[(size_t)256 * NKT0 * 2 * 16];   // 6 MB
__device__ uint4 g_Wf1[(size_t)256 * NKT1 * 2 * 16];   // 8 MB
__device__ float g_b0[G_];
__device__ float g_b1[G_];
// Activations, PRE-SPLIT fragment order: per ktile block = [mg8(8)][s=hi/lo(2)][lane(32)] uint4
__device__ uint4 g_xf[(size_t)T_ * 16 * 512];          // 64 MB
__device__ uint4 g_h0f[2][32 * 512];
__device__ uint4 g_h1f[2][32 * 512];
__device__ unsigned g_count;
__device__ unsigned g_release;

// ---------------- helpers -------------------------------------------------------
__device__ __forceinline__ float sigm(float v) {
    return __fdividef(1.f, 1.f + __expf(-v));
}
__device__ __forceinline__ float ftanh(float x) {
    float e = __expf(-2.f * fabsf(x));
    float t = __fdividef(1.f - e, 1.f + e);
    return copysignf(t, x);
}

__device__ __forceinline__ uint32_t pack_split(float v) {
    __nv_bfloat16 h = __float2bfloat16(v);
    __nv_bfloat16 l = __float2bfloat16(v - __bfloat162float(h));
    return (uint32_t)__bfloat16_as_ushort(h) |
           ((uint32_t)__bfloat16_as_ushort(l) << 16);
}

__device__ __forceinline__ uint32_t prmt(uint32_t a, uint32_t b, uint32_t c) {
    uint32_t r;
    asm("prmt.b32 %0, %1, %2, %3;" : "=r"(r) : "r"(a), "r"(b), "r"(c));
    return r;
}

__device__ __forceinline__ void mma16816(float* d, const uint32_t* a, uint2 b) {
    asm volatile(
        "mma.sync.aligned.m16n8k16.row.col.f32.bf16.bf16.f32 "
        "{%0,%1,%2,%3}, {%4,%5,%6,%7}, {%8,%9}, {%0,%1,%2,%3};"
        : "+f"(d[0]), "+f"(d[1]), "+f"(d[2]), "+f"(d[3])
        : "r"(a[0]), "r"(a[1]), "r"(a[2]), "r"(a[3]), "r"(b.x), "r"(b.y));
}

__device__ __forceinline__ void gridBarrier(unsigned target) {
    __syncthreads();
    if (threadIdx.x == 0) {
        __threadfence();
        unsigned t = atomicAdd(&g_count, 1u);
        if (t == (unsigned)(NCTA - 1)) {
            g_count = 0;
            __threadfence();
            atomicAdd(&g_release, 1u);
        } else {
            while ((int)(*(volatile unsigned*)&g_release - target) < 0) {}
        }
        __threadfence();
    }
    __syncthreads();
}

// bf16-split store of W[np][k] into ktile-pair fragment layout (hi plane s=0, lo s=1)
__device__ __forceinline__ void wf_store(__nv_bfloat16* base, int NKTP,
                                         int np, int k, float v) {
    __nv_bfloat16 h = __float2bfloat16(v);
    __nv_bfloat16 l = __float2bfloat16(v - __bfloat162float(h));
    int ntg = np >> 3;
    int ln = ((np & 7) << 2) | ((k >> 1) & 3);
    int kt = k >> 4, ktp = kt >> 1, kh = kt & 1;
    int b = (k >> 3) & 1, e = k & 1;
    size_t o = ((((size_t)ntg * NKTP + ktp) * 2) * 32 + ln) * 8 + kh * 4 + b * 2 + e;
    base[o] = h;
    base[o + 256] = l;   // lo plane: +32 uint4
}

// ---------------- prep kernels ---------------------------------------------------
__global__ void prep_x(const float* __restrict__ x) {
    __shared__ float sx[16 * 256];
    int blk = blockIdx.x;           // t*8 + mg8
    int t = blk >> 3, mg = blk & 7;
    int tid = threadIdx.x;
    for (int i = tid; i < 16 * 256; i += 256) {
        int r = i >> 8, d = i & 255;
        sx[i] = x[(size_t)(mg * 16 + r) * T_ * D_ + (size_t)t * D_ + d];
    }
    __syncthreads();
    uint4* out = g_xf + (size_t)t * 16 * 512;
    for (int i = tid; i < 512; i += 256) {
        int kt = i >> 5, lane = i & 31;
        uint32_t hi[4], lo[4];
#pragma unroll
        for (int j = 0; j < 4; ++j) {
            int r = (lane >> 2) + (j & 1) * 8;
            int d0 = kt * 16 + (j >> 1) * 8 + ((lane & 3) << 1);
            uint32_t p0 = pack_split(sx[r * 256 + d0]);
            uint32_t p1 = pack_split(sx[r * 256 + d0 + 1]);
            hi[j] = prmt(p0, p1, 0x5410);
            lo[j] = prmt(p0, p1, 0x7632);
        }
        out[(size_t)kt * 512 + mg * 64 + lane] =
            make_uint4(hi[0], hi[1], hi[2], hi[3]);
        out[(size_t)kt * 512 + mg * 64 + 32 + lane] =
            make_uint4(lo[0], lo[1], lo[2], lo[3]);
    }
}

__global__ void prep_w0(const float* __restrict__ wx0, const float* __restrict__ projw,
                        const float* __restrict__ projb, const float* __restrict__ bx0,
                        const float* __restrict__ bh0) {
    int np = blockIdx.x;
    int jcol = np >> 2, q = np & 3;
    int n = q * H_ + jcol;
    int d = threadIdx.x;
    const float* wrow = wx0 + (size_t)n * D_;
    float acc = 0.f;
    for (int j = 0; j < D_; ++j) acc += wrow[j] * projw[(size_t)j * D_ + d];
    wf_store((__nv_bfloat16*)g_Wf0, NKT0 / 2, np, d, acc);
    if (d == 0) {
        float bb = bx0[n] + bh0[n];
        for (int j = 0; j < D_; ++j) bb += wrow[j] * projb[j];
        g_b0[np] = bb;
    }
}

__global__ void prep_rest(const float* __restrict__ wh0, const float* __restrict__ wx1,
                          const float* __restrict__ wh1, const float* __restrict__ bx1,
                          const float* __restrict__ bh1) {
    const int total = G_ * H_ + G_ * K1_ + G_;
    for (int i = blockIdx.x * blockDim.x + threadIdx.x; i < total;
         i += gridDim.x * blockDim.x) {
        if (i < G_ * H_) {
            int np = i / H_, k = i % H_;
            int n = (np & 3) * H_ + (np >> 2);
            wf_store((__nv_bfloat16*)g_Wf0, NKT0 / 2, np, D_ + k,
                     wh0[(size_t)n * H_ + k]);
        } else if (i < G_ * H_ + G_ * K1_) {
            int r = i - G_ * H_;
            int np = r / K1_, k = r % K1_;
            int n = (np & 3) * H_ + (np >> 2);
            float v = (k < H_) ? wx1[(size_t)n * H_ + k]
                               : wh1[(size_t)n * H_ + (k - H_)];
            wf_store((__nv_bfloat16*)g_Wf1, NKT1 / 2, np, k, v);
        } else {
            int np = i - G_ * H_ - G_ * K1_;
            int n = (np & 3) * H_ + (np >> 2);
            g_b1[np] = bx1[n] + bh1[n];
        }
    }
}

// ---------------- one LSTM phase: 4-way K-split, M=32/warp -----------------------
// 16 warps = 4 M-groups x 4 K-groups; each warp M=32 (2 m-tiles) x N=32 (4 nt).
template <int NKT>
__device__ void lstm_phase(const uint32_t* __restrict__ sW,
    const uint4* __restrict__ pA, const uint4* __restrict__ pB, int split,
    uint4* __restrict__ hOutF, float* cst,
    const float* __restrict__ sbias, float* __restrict__ part,
    uint32_t* __restrict__ bounce, int lc) {
    constexpr int NKTP = NKT / 2;   // total ktile pairs (weight layout stride)
    constexpr int NKTH = NKT / 4;   // ktiles per k-group
    const int tid = threadIdx.x;
    const int lane = tid & 31, w = tid >> 5;
    const int mg = w & 3, kgrp = w >> 2;
    const int ktbase = kgrp * NKTH;

    float acc[2][4][4];
#pragma unroll
    for (int mt = 0; mt < 2; ++mt)
#pragma unroll
        for (int nt = 0; nt < 4; ++nt)
#pragma unroll
            for (int e = 0; e < 4; ++e) acc[mt][nt][e] = 0.f;

    uint4 ab[2][4];   // ring of 2 ktiles x [mt*2 + s]
#pragma unroll
    for (int p = 0; p < 2; ++p) {
        int kt = ktbase + p;
        const uint4* base = (kt < split) ? pA + (size_t)kt * 512
                                         : pB + (size_t)(kt - split) * 512;
#pragma unroll
        for (int mt = 0; mt < 2; ++mt) {
            const uint4* s = base + (2 * mg + mt) * 64 + lane;
            ab[p][mt * 2 + 0] = s[0];
            ab[p][mt * 2 + 1] = s[32];
        }
    }
    const uint4* sW4 = (const uint4*)sW;
    uint4 bh[4], bl[4];

#pragma unroll 2
    for (int kk = 0; kk < NKTH; ++kk) {
        int ktg = ktbase + kk;
        int half = kk & 1;               // ktbase even (NKTH = 12 or 16)
        if (half == 0) {
            int ktp = ktg >> 1;
#pragma unroll
            for (int nt = 0; nt < 4; ++nt) {
                const uint4* wp = sW4 + (size_t)((nt * NKTP + ktp) * 2) * 32 + lane;
                bh[nt] = wp[0];
                bl[nt] = wp[32];
            }
        }
        uint4* cur = ab[kk & 1];
        // pass 1: hi·hi
#pragma unroll
        for (int mt = 0; mt < 2; ++mt)
#pragma unroll
            for (int nt = 0; nt < 4; ++nt) {
                uint2 b2 = half ? make_uint2(bh[nt].z, bh[nt].w)
                                : make_uint2(bh[nt].x, bh[nt].y);
                mma16816(acc[mt][nt], (const uint32_t*)&cur[mt * 2 + 0], b2);
            }
        // pass 2: lo·hi
#pragma unroll
        for (int mt = 0; mt < 2; ++mt)
#pragma unroll
            for (int nt = 0; nt < 4; ++nt) {
                uint2 b2 = half ? make_uint2(bh[nt].z, bh[nt].w)
                                : make_uint2(bh[nt].x, bh[nt].y);
                mma16816(acc[mt][nt], (const uint32_t*)&cur[mt * 2 + 1], b2);
            }
        // pass 3: hi·lo
#pragma unroll
        for (int mt = 0; mt < 2; ++mt)
#pragma unroll
            for (int nt = 0; nt < 4; ++nt) {
                uint2 b2 = half ? make_uint2(bl[nt].z, bl[nt].w)
                                : make_uint2(bl[nt].x, bl[nt].y);
                mma16816(acc[mt][nt], (const uint32_t*)&cur[mt * 2 + 0], b2);
            }
        if (kk + 2 < NKTH) {
            int kn = ktg + 2;
            const uint4* base = (kn < split) ? pA + (size_t)kn * 512
                                             : pB + (size_t)(kn - split) * 512;
#pragma unroll
            for (int mt = 0; mt < 2; ++mt) {
                const uint4* s = base + (2 * mg + mt) * 64 + lane;
                cur[mt * 2 + 0] = s[0];
                cur[mt * 2 + 1] = s[32];
            }
        }
    }

    // deposit all partials (padded 132-float blocks; conflict-free float4 stores)
#pragma unroll
    for (int mt = 0; mt < 2; ++mt)
#pragma unroll
        for (int nt = 0; nt < 4; ++nt) {
            int blk = ((kgrp * 4 + mg) * 2 + mt) * 4 + nt;
            *(float4*)(part + blk * 132 + lane * 4) =
                make_float4(acc[mt][nt][0], acc[mt][nt][1],
                            acc[mt][nt][2], acc[mt][nt][3]);
        }
    __syncthreads();

    // distributed epilogue: each thread owns 2 cells (same row, jc0 & jc0+1)
    {
        int row = tid >> 2;
        int jc0 = (tid & 3) * 2;
        int mg2 = row >> 5, rw = row & 31;
        int mt = (rw >> 4) & 1, rp = (rw >> 3) & 1, rlo = rw & 7;
        int nt = jc0 >> 1;
        float g8[8];
#pragma unroll
        for (int e = 0; e < 8; ++e) g8[e] = 0.f;
#pragma unroll
        for (int kg = 0; kg < 4; ++kg) {
            int blk = ((kg * 4 + mg2) * 2 + mt) * 4 + nt;
            const float* bp = part + blk * 132 + rlo * 16 + rp * 2;
#pragma unroll
            for (int q = 0; q < 4; ++q) {
                float2 v = *(const float2*)(bp + q * 4);
                g8[q * 2]     += v.x;
                g8[q * 2 + 1] += v.y;
            }
        }
        uint32_t hv[2];
#pragma unroll
        for (int c2 = 0; c2 < 2; ++c2) {
            int jc = jc0 + c2;
            float iv = g8[c2 * 4 + 0] + sbias[jc * 4 + 0];
            float fv = g8[c2 * 4 + 1] + sbias[jc * 4 + 1];
            float gv = g8[c2 * 4 + 2] + sbias[jc * 4 + 2];
            float ov = g8[c2 * 4 + 3] + sbias[jc * 4 + 3];
            float cn = sigm(fv) * cst[c2] + sigm(iv) * ftanh(gv);
            cst[c2] = cn;
            hv[c2] = pack_split(sigm(ov) * ftanh(cn));
        }
        *(uint2*)(bounce + row * 8 + jc0) = make_uint2(hv[0], hv[1]);
    }
    __syncthreads();
    if (tid < 256) {   // pre-split h store: hi/lo uint2 per thread, coalesced
        int w8 = tid >> 5;
        int ln = tid & 31;
        int rlo = ln >> 2, q2 = ln & 3;
        int row = w8 * 16 + rlo;
        uint32_t c0 = bounce[row * 8 + 2 * q2];
        uint32_t c1 = bounce[row * 8 + 2 * q2 + 1];
        uint32_t c2 = bounce[(row + 8) * 8 + 2 * q2];
        uint32_t c3 = bounce[(row + 8) * 8 + 2 * q2 + 1];
        uint2 hiv = make_uint2(prmt(c0, c1, 0x5410), prmt(c2, c3, 0x5410));
        uint2 lov = make_uint2(prmt(c0, c1, 0x7632), prmt(c2, c3, 0x7632));
        int kt = lc >> 1, half = lc & 1;
        uint2* o = (uint2*)hOutF;
        size_t bidx = (size_t)kt * 512 + w8 * 64 + ln;
        o[2 * bidx + half] = hiv;
        o[2 * (bidx + 32) + half] = lov;
    }
}

// ---------------- persistent main kernel -----------------------------------------
__global__ void __launch_bounds__(NTHR, 1) lstm_main() {
    extern __shared__ uint32_t smw[];          // part | bounce | weights
    __shared__ float s_bias[32];
    float* part = (float*)smw;                 // 67584 B (padded partials)
    uint32_t* bounce = smw + OFF_BOUNCE;       // 4 KB
    uint32_t* sW = smw + OFF_W;                // weights

    const int cta = blockIdx.x, tid = threadIdx.x;
    const bool isL1 = (cta >= 64);
    const int lc = isL1 ? cta - 64 : cta;

    // load resident weight fragment slice (contiguous)
    {
        const uint4* src = isL1 ? g_Wf1 : g_Wf0;
        const int NKT = isL1 ? NKT1 : NKT0;
        const uint4* s = src + (size_t)lc * NKT * 128;
        uint4* d = (uint4*)sW;
        for (int i = tid; i < NKT * 128; i += NTHR) d[i] = s[i];
        const float* gb = isL1 ? g_b1 : g_b0;
        if (tid < 32) s_bias[tid] = gb[lc * 32 + tid];
    }
    // zero h fragment buffers each launch (deterministic)
    {
        uint32_t* hz0 = (uint32_t*)g_h0f;
        uint32_t* hz1 = (uint32_t*)g_h1f;
        for (int i = cta * NTHR + tid; i < 2 * 32 * 512 * 4; i += NCTA * NTHR) {
            hz0[i] = 0u;
            hz1[i] = 0u;
        }
    }

    unsigned relBase = *(volatile unsigned*)&g_release;
    unsigned gen = 0;
    float cst[2] = {0.f, 0.f};

    gridBarrier(relBase + ++gen);

    for (int phase = 0; phase <= T_; ++phase) {
        if (!isL1) {
            if (phase < T_) {
                int t = phase;
                lstm_phase<NKT0>(sW, g_xf + (size_t)t * 16 * 512,
                                 g_h0f[(t & 1) ^ 1], 16,
                                 g_h0f[t & 1], cst, s_bias, part, bounce, lc);
            }
        } else if (phase >= 1) {
            int t = phase - 1;
            lstm_phase<NKT1>(sW, g_h0f[t & 1],
                             g_h1f[(t & 1) ^ 1], 32,
                             g_h1f[t & 1], cst, s_bias, part, bounce, lc);
        }
        gridBarrier(relBase + ++gen);
    }
}

// ---------------- FC head ----------------------------------------------------------
__global__ void fc_head(const float* __restrict__ fc1w, const float* __restrict__ fc1b,
                        const float* __restrict__ fc2w, const float* __restrict__ fc2b,
                        float* __restrict__ out) {
    __shared__ float hsh[H_];
    __shared__ float hid[32];
    int b = blockIdx.x, tid = threadIdx.x;
    const uint32_t* hf = (const uint32_t*)g_h1f[1];   // t=511 odd -> buf1
#pragma unroll
    for (int rr = 0; rr < 2; ++rr) {
        int col = tid + rr * 256;
        int kt = col >> 4, k16 = col & 15;
        int half = k16 >> 3, q = (k16 >> 1) & 3, e = k16 & 1;
        int r = b & 15, mg = b >> 4;
        int lane2 = ((r & 7) << 2) | q;
        int j = half * 2 + ((r >> 3) & 1);
        size_t u32i = ((size_t)kt * 512 + mg * 64 + lane2) * 4 + j;
        uint32_t uh = hf[u32i];
        uint32_t ul = hf[u32i + 128];
        unsigned short sh = e ? (unsigned short)(uh >> 16) : (unsigned short)(uh & 0xFFFFu);
        unsigned short sl = e ? (unsigned short)(ul >> 16) : (unsigned short)(ul & 0xFFFFu);
        hsh[col] = __bfloat162float(__ushort_as_bfloat16(sh)) +
                   __bfloat162float(__ushort_as_bfloat16(sl));
    }
    __syncthreads();
    int w = tid >> 5, lane = tid & 31;
    for (int j = w; j < 32; j += 8) {
        const float* wr = fc1w + (size_t)j * H_;
        float s = 0.f;
        for (int k = lane; k < H_; k += 32) s += hsh[k] * wr[k];
#pragma unroll
        for (int off = 16; off; off >>= 1) s += __shfl_xor_sync(0xffffffffu, s, off);
        if (lane == 0) hid[j] = fmaxf(s + fc1b[j], 0.f) * fc2w[j];
    }
    __syncthreads();
    if (tid < 32) {
        float v = hid[tid];
#pragma unroll
        for (int off = 16; off; off >>= 1) v += __shfl_xor_sync(0xffffffffu, v, off);
        if (tid == 0) out[b] = v + fc2b[0];
    }
}

// ---------------- launch -------------------------------------------------------------
extern "C" void kernel_launch(void* const* d_in, const int* in_sizes, int n_in,
                              void* d_out, int out_size) {
    const float* x     = (const float*)d_in[0];
    const float* projw = (const float*)d_in[1];
    const float* projb = (const float*)d_in[2];
    const float* wx0   = (const float*)d_in[3];
    const float* bx0   = (const float*)d_in[4];
    const float* wh0   = (const float*)d_in[5];
    const float* bh0   = (const float*)d_in[6];
    const float* wx1   = (const float*)d_in[7];
    const float* bx1   = (const float*)d_in[8];
    const float* wh1   = (const float*)d_in[9];
    const float* bh1   = (const float*)d_in[10];
    const float* fc1w  = (const float*)d_in[11];
    const float* fc1b  = (const float*)d_in[12];
    const float* fc2w  = (const float*)d_in[13];
    const float* fc2b  = (const float*)d_in[14];
    float* out = (float*)d_out;

    const int SMEM_BYTES = OFF_W * 4 + NKT1 * 128 * 16;  // 71680 + 131072 = 202752
    cudaFuncSetAttribute(lstm_main, cudaFuncAttributeMaxDynamicSharedMemorySize,
                         SMEM_BYTES);

    prep_x<<<T_ * 8, 256>>>(x);
    prep_w0<<<G_, D_>>>(wx0, projw, projb, bx0, bh0);
    prep_rest<<<2048, 256>>>(wh0, wx1, wh1, bx1, bh1);
    lstm_main<<<NCTA, NTHR, SMEM_BYTES>>>();
    fc_head<<<B_, 256>>>(fc1w, fc1b, fc2w, fc2b, out);
}